// round 10
// baseline (speedup 1.0000x reference)
#include <cuda_runtime.h>
#include <cuda_fp16.h>
#include <cuda_bf16.h>
#include <math.h>

#define N_NODES 50000
#define N_EDGES 1600000
#define IN_DIM  128
#define HID     64
#define EPS     1e-6f

#define SCAN_T   1024
#define NTILES   ((N_NODES + SCAN_T - 1) / SCAN_T)   // 49
#define FLAG     (1 << 30)
#define VMASK    (FLAG - 1)

// ---------------- scratch (no allocations allowed) ----------------
__device__ int   g_is64;                 // 1 if edge_index is int64, 0 if int32
__device__ int   g_deg[N_NODES];
__device__ int   g_rowptr[N_NODES + 1];
__device__ int   g_cursor[N_NODES];
__device__ float g_invdeg[N_NODES];
__device__ int   g_csr_src[N_EDGES];
__device__ int   g_tile_state[64];       // lookback: sum | FLAG

__device__ float  g_s[N_NODES * HID];
__device__ __half g_th[N_NODES * HID];   // fp16 messages (aggregate input)
__device__ float  g_hA[N_NODES * HID];
__device__ float  g_hB[N_NODES * HID];

__device__ __forceinline__ int edge_at(const void* __restrict__ ei, int idx, int is64) {
    if (is64) return (int)((const long long*)ei)[idx];
    return ((const int*)ei)[idx];
}

// ---------------- init: zero deg + lookback state, detect edge dtype ----------------
// JAX x64-disabled silently downgrades jnp.int64 -> int32. Valid node ids are
// < 50000; interpret first 256 entries as int64 — any out-of-range => int32.
__global__ void init_kernel(const void* __restrict__ ei) {
    int i = blockIdx.x * blockDim.x + threadIdx.x;
    if (i < N_NODES) g_deg[i] = 0;
    if (blockIdx.x == 1 && threadIdx.x < 64) g_tile_state[threadIdx.x] = 0;
    if (blockIdx.x == 0) {
        const long long* p = (const long long*)ei;
        long long v = p[threadIdx.x];
        int bad = (v < 0 || v >= (long long)N_NODES) ? 1 : 0;
        int anybad = __syncthreads_or(bad);
        if (threadIdx.x == 0) g_is64 = anybad ? 0 : 1;
    }
}

__global__ void count_deg_kernel(const void* __restrict__ ei) {
    int e = blockIdx.x * blockDim.x + threadIdx.x;
    int is64 = g_is64;
    if (e < N_EDGES) {
        int dst = edge_at(ei, N_EDGES + e, is64);
        atomicAdd(&g_deg[dst], 1);
    }
}

// ---------------- fused scan: decoupled lookback, one kernel ----------------
// 49 blocks x 1024 threads, all resident (49 < 148 SMs) -> no deadlock.
// Each block: intra-block scan of its 1024 degrees, publish flagged tile sum,
// parallel-poll predecessors, add prefix, write rowptr/cursor/invdeg.
__global__ void scan_fused_kernel() {
    __shared__ int warp_sums[32];
    __shared__ int red[2];
    __shared__ int s_pref;
    int b = blockIdx.x, tid = threadIdx.x;
    int lane = tid & 31, wid = tid >> 5;
    int idx = b * SCAN_T + tid;
    int d = (idx < N_NODES) ? g_deg[idx] : 0;

    // intra-block inclusive scan
    int v = d;
    #pragma unroll
    for (int o = 1; o < 32; o <<= 1) {
        int u = __shfl_up_sync(0xffffffffu, v, o);
        if (lane >= o) v += u;
    }
    if (lane == 31) warp_sums[wid] = v;
    __syncthreads();
    if (wid == 0) {
        int w = warp_sums[lane];
        #pragma unroll
        for (int o = 1; o < 32; o <<= 1) {
            int u = __shfl_up_sync(0xffffffffu, w, o);
            if (lane >= o) w += u;
        }
        warp_sums[lane] = w;
    }
    __syncthreads();

    // publish tile total immediately (decoupled from our own prefix wait)
    if (tid == 0) atomicExch(&g_tile_state[b], warp_sums[31] | FLAG);

    // parallel poll of predecessors (tid < b), 2-warp reduce
    if (tid < 64) {
        int val = 0;
        if (tid < b) {
            int t;
            do { t = atomicAdd(&g_tile_state[tid], 0); } while (!(t & FLAG));
            val = t & VMASK;
        }
        #pragma unroll
        for (int o = 16; o; o >>= 1) val += __shfl_xor_sync(0xffffffffu, val, o);
        if ((tid & 31) == 0) red[tid >> 5] = val;
    }
    __syncthreads();
    if (tid == 0) s_pref = red[0] + red[1];
    __syncthreads();

    if (idx < N_NODES) {
        int excl = s_pref + (v - d) + (wid ? warp_sums[wid - 1] : 0);
        g_rowptr[idx] = excl;
        g_cursor[idx] = excl;
        g_invdeg[idx] = 1.0f / (float)max(d, 1);
    }
    if (b == 0 && tid == 0) g_rowptr[N_NODES] = N_EDGES;
}

__global__ void fill_csr_kernel(const void* __restrict__ ei) {
    int e = blockIdx.x * blockDim.x + threadIdx.x;
    int is64 = g_is64;
    if (e < N_EDGES) {
        int src = edge_at(ei, e, is64);
        int dst = edge_at(ei, N_EDGES + e, is64);
        int pos = atomicAdd(&g_cursor[dst], 1);
        g_csr_src[pos] = src;
    }
}

// ---------------- persistent fused dual GEMM: s = h@ws (fp32), t = h@wn (fp16) ----
// Fixed grid (2 blocks/SM); each block loads weights once, then loops node tiles.
template<int DIN>
__global__ void dual_gemm_kernel(const float* __restrict__ h,
                                 const float* __restrict__ ws,
                                 const float* __restrict__ wn,
                                 float* __restrict__ s_out,
                                 __half* __restrict__ t_out) {
    extern __shared__ float smem[];
    float* ws_sh = smem;                       // DIN*64
    float* wn_sh = smem + DIN * 64;            // DIN*64
    float* h_sh  = smem + 2 * DIN * 64;        // 32*DIN

    int tid = threadIdx.x;
    int tx  = tid & 31;
    int ty  = tid >> 5;

    const float4* ws4 = (const float4*)ws;
    const float4* wn4 = (const float4*)wn;
    #pragma unroll 4
    for (int i = tid; i < DIN * 16; i += 256) {
        ((float4*)ws_sh)[i] = ws4[i];
        ((float4*)wn_sh)[i] = wn4[i];
    }
    __syncthreads();

    const int NT32 = (N_NODES + 31) / 32;      // 32-node tiles
    for (int t32 = blockIdx.x; t32 < NT32; t32 += gridDim.x) {
        int nb = t32 * 32;
        int vn = min(32, N_NODES - nb);
        int valid_f4 = vn * (DIN / 4);

        const float4* hsrc = (const float4*)(h + (size_t)nb * DIN);
        for (int i = tid; i < 32 * (DIN / 4); i += 256)
            ((float4*)h_sh)[i] = (i < valid_f4) ? hsrc[i] : make_float4(0.f, 0.f, 0.f, 0.f);
        __syncthreads();

        int row = ty * 4;
        float2 as0 = {0,0}, as1 = {0,0}, as2 = {0,0}, as3 = {0,0};
        float2 at0 = {0,0}, at1 = {0,0}, at2 = {0,0}, at3 = {0,0};
        const float4* h0 = (const float4*)(h_sh + (row + 0) * DIN);
        const float4* h1 = (const float4*)(h_sh + (row + 1) * DIN);
        const float4* h2 = (const float4*)(h_sh + (row + 2) * DIN);
        const float4* h3 = (const float4*)(h_sh + (row + 3) * DIN);

        #pragma unroll 4
        for (int kq = 0; kq < DIN / 4; ++kq) {
            float4 v0 = h0[kq], v1 = h1[kq], v2 = h2[kq], v3 = h3[kq];
            const float* e0 = (const float*)&v0;
            const float* e1 = (const float*)&v1;
            const float* e2 = (const float*)&v2;
            const float* e3 = (const float*)&v3;
            #pragma unroll
            for (int j = 0; j < 4; ++j) {
                int k = kq * 4 + j;
                float2 wsv = *(const float2*)&ws_sh[k * 64 + 2 * tx];
                float2 wnv = *(const float2*)&wn_sh[k * 64 + 2 * tx];
                float a0 = e0[j], a1 = e1[j], a2 = e2[j], a3 = e3[j];
                as0.x = fmaf(a0, wsv.x, as0.x); as0.y = fmaf(a0, wsv.y, as0.y);
                as1.x = fmaf(a1, wsv.x, as1.x); as1.y = fmaf(a1, wsv.y, as1.y);
                as2.x = fmaf(a2, wsv.x, as2.x); as2.y = fmaf(a2, wsv.y, as2.y);
                as3.x = fmaf(a3, wsv.x, as3.x); as3.y = fmaf(a3, wsv.y, as3.y);
                at0.x = fmaf(a0, wnv.x, at0.x); at0.y = fmaf(a0, wnv.y, at0.y);
                at1.x = fmaf(a1, wnv.x, at1.x); at1.y = fmaf(a1, wnv.y, at1.y);
                at2.x = fmaf(a2, wnv.x, at2.x); at2.y = fmaf(a2, wnv.y, at2.y);
                at3.x = fmaf(a3, wnv.x, at3.x); at3.y = fmaf(a3, wnv.y, at3.y);
            }
        }

        #pragma unroll
        for (int n = 0; n < 4; ++n) {
            int node = nb + row + n;
            if (node < N_NODES) {
                float2 sv = (n == 0) ? as0 : (n == 1) ? as1 : (n == 2) ? as2 : as3;
                float2 tv = (n == 0) ? at0 : (n == 1) ? at1 : (n == 2) ? at2 : at3;
                *(float2*)&s_out[(size_t)node * 64 + 2 * tx] = sv;
                *(__half2*)&t_out[(size_t)node * 64 + 2 * tx] = __float22half2_rn(tv);
            }
        }
        __syncthreads();
    }
}

// ---------------- aggregate + combine + normalize ----------------
// warp per node; lane handles feature pair (2*lane, 2*lane+1); 4-edge unroll.
__global__ void agg_combine_kernel(const __half* __restrict__ t,
                                   const float* __restrict__ smat,
                                   float* __restrict__ hout) {
    int warp = (blockIdx.x * blockDim.x + threadIdx.x) >> 5;
    int lane = threadIdx.x & 31;
    if (warp >= N_NODES) return;

    int beg = g_rowptr[warp];
    int end = g_rowptr[warp + 1];
    const __half2* t2 = (const __half2*)t;

    float ax = 0.f, ay = 0.f, bx = 0.f, by = 0.f;
    int i = beg;
    for (; i + 4 <= end; i += 4) {
        int s0 = __ldg(&g_csr_src[i]);
        int s1 = __ldg(&g_csr_src[i + 1]);
        int s2 = __ldg(&g_csr_src[i + 2]);
        int s3 = __ldg(&g_csr_src[i + 3]);
        float2 u0 = __half22float2(t2[(size_t)s0 * 32 + lane]);
        float2 u1 = __half22float2(t2[(size_t)s1 * 32 + lane]);
        float2 u2 = __half22float2(t2[(size_t)s2 * 32 + lane]);
        float2 u3 = __half22float2(t2[(size_t)s3 * 32 + lane]);
        ax += u0.x; ay += u0.y;
        bx += u1.x; by += u1.y;
        ax += u2.x; ay += u2.y;
        bx += u3.x; by += u3.y;
    }
    for (; i < end; ++i) {
        int s0 = __ldg(&g_csr_src[i]);
        float2 u = __half22float2(t2[(size_t)s0 * 32 + lane]);
        ax += u.x; ay += u.y;
    }
    ax += bx; ay += by;

    float id = g_invdeg[warp];
    float2 sm = ((const float2*)smat)[(size_t)warp * 32 + lane];
    float v0 = fmaxf(sm.x + ax * id, 0.f);
    float v1 = fmaxf(sm.y + ay * id, 0.f);

    float ss = v0 * v0 + v1 * v1;
    #pragma unroll
    for (int o = 16; o; o >>= 1) ss += __shfl_xor_sync(0xffffffffu, ss, o);
    float scale = 1.f / (sqrtf(ss) + EPS);

    float2 r; r.x = v0 * scale; r.y = v1 * scale;
    ((float2*)hout)[(size_t)warp * 32 + lane] = r;
}

// ---------------- MLP head: relu(h@mw1+mb1) -> sigmoid(.@mw2+mb2) ----------------
__global__ void head_kernel(const float* __restrict__ h,
                            const float* __restrict__ mw1,
                            const float* __restrict__ mb1,
                            const float* __restrict__ mw2,
                            const float* __restrict__ mb2,
                            float* __restrict__ out) {
    __shared__ float w1s[64 * 32];
    __shared__ float b1s[32];
    __shared__ float w2s[32];
    __shared__ float b2s;

    int tid = threadIdx.x;
    for (int i = tid; i < 64 * 32; i += blockDim.x) w1s[i] = mw1[i];
    if (tid < 32) { b1s[tid] = mb1[tid]; w2s[tid] = mw2[tid]; }
    if (tid == 0) b2s = mb2[0];
    __syncthreads();

    int lane = tid & 31;
    int warp0 = (blockIdx.x * blockDim.x + tid) >> 5;
    int nwarps = (gridDim.x * blockDim.x) >> 5;

    for (int node = warp0; node < N_NODES; node += nwarps) {
        float h0 = h[(size_t)node * 64 + lane];
        float h1 = h[(size_t)node * 64 + lane + 32];

        float acc = b1s[lane];
        #pragma unroll
        for (int k = 0; k < 32; ++k) {
            float hk = __shfl_sync(0xffffffffu, h0, k);
            acc = fmaf(hk, w1s[k * 32 + lane], acc);
        }
        #pragma unroll
        for (int k = 0; k < 32; ++k) {
            float hk = __shfl_sync(0xffffffffu, h1, k);
            acc = fmaf(hk, w1s[(k + 32) * 32 + lane], acc);
        }
        acc = fmaxf(acc, 0.f);

        float p = acc * w2s[lane];
        #pragma unroll
        for (int o = 16; o; o >>= 1) p += __shfl_xor_sync(0xffffffffu, p, o);

        if (lane == 0) {
            float z = p + b2s;
            out[node] = 1.f / (1.f + __expf(-z));
        }
    }
}

// ---------------- launch ----------------
extern "C" void kernel_launch(void* const* d_in, const int* in_sizes, int n_in,
                              void* d_out, int out_size) {
    const float* x   = (const float*)d_in[0];
    const void*  ei  = (const void*)d_in[1];   // int32 or int64, detected on device
    const float* w0s = (const float*)d_in[2];
    const float* w0n = (const float*)d_in[3];
    const float* w1s = (const float*)d_in[4];
    const float* w1n = (const float*)d_in[5];
    const float* w2s = (const float*)d_in[6];
    const float* w2n = (const float*)d_in[7];
    const float* mw1 = (const float*)d_in[8];
    const float* mb1 = (const float*)d_in[9];
    const float* mw2 = (const float*)d_in[10];
    const float* mb2 = (const float*)d_in[11];
    float* out = (float*)d_out;

    float *d_s, *d_hA, *d_hB;
    __half* d_th;
    cudaGetSymbolAddress((void**)&d_s,  g_s);
    cudaGetSymbolAddress((void**)&d_th, g_th);
    cudaGetSymbolAddress((void**)&d_hA, g_hA);
    cudaGetSymbolAddress((void**)&d_hB, g_hB);

    // dynamic smem: DIN*160 floats. Set attributes unconditionally every call
    // (idempotent, not a graph node) — no static guards allowed.
    const int SMEM128 = 128 * 160 * 4;   // 81920
    const int SMEM64  = 64 * 160 * 4;    // 40960
    cudaFuncSetAttribute(dual_gemm_kernel<128>,
                         cudaFuncAttributeMaxDynamicSharedMemorySize, SMEM128);
    cudaFuncSetAttribute(dual_gemm_kernel<64>,
                         cudaFuncAttributeMaxDynamicSharedMemorySize, SMEM64);

    const int EB = (N_EDGES + 255) / 256;
    const int NB = (N_NODES + 255) / 256;
    const int GEMM_BLOCKS = 296;                  // 2 per SM, persistent
    const int WB = (N_NODES * 32 + 255) / 256;    // warp-per-node kernels

    // CSR build (once per launch)
    init_kernel<<<NB, 256>>>(ei);
    count_deg_kernel<<<EB, 256>>>(ei);
    scan_fused_kernel<<<NTILES, 1024>>>();
    fill_csr_kernel<<<EB, 256>>>(ei);

    // layer 0 (input x, DIN=128)
    dual_gemm_kernel<128><<<GEMM_BLOCKS, 256, SMEM128>>>(x, w0s, w0n, d_s, d_th);
    agg_combine_kernel<<<WB, 256>>>(d_th, d_s, d_hA);

    // layer 1
    dual_gemm_kernel<64><<<GEMM_BLOCKS, 256, SMEM64>>>(d_hA, w1s, w1n, d_s, d_th);
    agg_combine_kernel<<<WB, 256>>>(d_th, d_s, d_hB);

    // layer 2
    dual_gemm_kernel<64><<<GEMM_BLOCKS, 256, SMEM64>>>(d_hB, w2s, w2n, d_s, d_th);
    agg_combine_kernel<<<WB, 256>>>(d_th, d_s, d_hA);

    // head
    head_kernel<<<1024, 256>>>(d_hA, mw1, mb1, mw2, mb2, out);
}

// round 11
// speedup vs baseline: 1.1106x; 1.1106x over previous
#include <cuda_runtime.h>
#include <cuda_fp16.h>
#include <cuda_bf16.h>
#include <math.h>

#define N_NODES 50000
#define N_EDGES 1600000
#define IN_DIM  128
#define HID     64
#define EPS     1e-6f

#define SCAN_T   1024
#define NTILES   ((N_NODES + SCAN_T - 1) / SCAN_T)   // 49
#define FLAG     (1 << 30)
#define VMASK    (FLAG - 1)

// ---------------- scratch (no allocations allowed) ----------------
__device__ int   g_is64;                 // 1 if edge_index is int64, 0 if int32
__device__ int   g_deg[N_NODES];
__device__ int   g_rowptr[N_NODES + 1];
__device__ int   g_cursor[N_NODES];
__device__ float g_invdeg[N_NODES];
__device__ int   g_csr_src[N_EDGES];
__device__ int   g_tile_state[64];       // lookback: sum | FLAG

__device__ float  g_s[N_NODES * HID];
__device__ __half g_th[N_NODES * HID];   // fp16 messages (aggregate input)
__device__ float  g_hA[N_NODES * HID];
__device__ float  g_hB[N_NODES * HID];

__device__ __forceinline__ int edge_at(const void* __restrict__ ei, int idx, int is64) {
    if (is64) return (int)((const long long*)ei)[idx];
    return ((const int*)ei)[idx];
}

// ---------------- init: zero deg + lookback state, detect edge dtype ----------------
__global__ void init_kernel(const void* __restrict__ ei) {
    int i = blockIdx.x * blockDim.x + threadIdx.x;
    if (i < N_NODES) g_deg[i] = 0;
    if (blockIdx.x == 1 && threadIdx.x < 64) g_tile_state[threadIdx.x] = 0;
    if (blockIdx.x == 0) {
        const long long* p = (const long long*)ei;
        long long v = p[threadIdx.x];
        int bad = (v < 0 || v >= (long long)N_NODES) ? 1 : 0;
        int anybad = __syncthreads_or(bad);
        if (threadIdx.x == 0) g_is64 = anybad ? 0 : 1;
    }
}

__global__ void count_deg_kernel(const void* __restrict__ ei) {
    int e = blockIdx.x * blockDim.x + threadIdx.x;
    int is64 = g_is64;
    if (e < N_EDGES) {
        int dst = edge_at(ei, N_EDGES + e, is64);
        atomicAdd(&g_deg[dst], 1);
    }
}

// ---------------- fused scan: decoupled lookback, one kernel ----------------
__global__ void scan_fused_kernel() {
    __shared__ int warp_sums[32];
    __shared__ int red[2];
    __shared__ int s_pref;
    int b = blockIdx.x, tid = threadIdx.x;
    int lane = tid & 31, wid = tid >> 5;
    int idx = b * SCAN_T + tid;
    int d = (idx < N_NODES) ? g_deg[idx] : 0;

    int v = d;
    #pragma unroll
    for (int o = 1; o < 32; o <<= 1) {
        int u = __shfl_up_sync(0xffffffffu, v, o);
        if (lane >= o) v += u;
    }
    if (lane == 31) warp_sums[wid] = v;
    __syncthreads();
    if (wid == 0) {
        int w = warp_sums[lane];
        #pragma unroll
        for (int o = 1; o < 32; o <<= 1) {
            int u = __shfl_up_sync(0xffffffffu, w, o);
            if (lane >= o) w += u;
        }
        warp_sums[lane] = w;
    }
    __syncthreads();

    if (tid == 0) atomicExch(&g_tile_state[b], warp_sums[31] | FLAG);

    if (tid < 64) {
        int val = 0;
        if (tid < b) {
            int t;
            do { t = atomicAdd(&g_tile_state[tid], 0); } while (!(t & FLAG));
            val = t & VMASK;
        }
        #pragma unroll
        for (int o = 16; o; o >>= 1) val += __shfl_xor_sync(0xffffffffu, val, o);
        if ((tid & 31) == 0) red[tid >> 5] = val;
    }
    __syncthreads();
    if (tid == 0) s_pref = red[0] + red[1];
    __syncthreads();

    if (idx < N_NODES) {
        int excl = s_pref + (v - d) + (wid ? warp_sums[wid - 1] : 0);
        g_rowptr[idx] = excl;
        g_cursor[idx] = excl;
        g_invdeg[idx] = 1.0f / (float)max(d, 1);
    }
    if (b == 0 && tid == 0) g_rowptr[N_NODES] = N_EDGES;
}

__global__ void fill_csr_kernel(const void* __restrict__ ei) {
    int e = blockIdx.x * blockDim.x + threadIdx.x;
    int is64 = g_is64;
    if (e < N_EDGES) {
        int src = edge_at(ei, e, is64);
        int dst = edge_at(ei, N_EDGES + e, is64);
        int pos = atomicAdd(&g_cursor[dst], 1);
        g_csr_src[pos] = src;
    }
}

// ---------------- persistent fused dual GEMM: s = h@ws (fp32), t = h@wn (fp16) ----
template<int DIN>
__global__ void dual_gemm_kernel(const float* __restrict__ h,
                                 const float* __restrict__ ws,
                                 const float* __restrict__ wn,
                                 float* __restrict__ s_out,
                                 __half* __restrict__ t_out) {
    extern __shared__ float smem[];
    float* ws_sh = smem;                       // DIN*64
    float* wn_sh = smem + DIN * 64;            // DIN*64
    float* h_sh  = smem + 2 * DIN * 64;        // 32*DIN

    int tid = threadIdx.x;
    int tx  = tid & 31;
    int ty  = tid >> 5;

    const float4* ws4 = (const float4*)ws;
    const float4* wn4 = (const float4*)wn;
    #pragma unroll 4
    for (int i = tid; i < DIN * 16; i += 256) {
        ((float4*)ws_sh)[i] = ws4[i];
        ((float4*)wn_sh)[i] = wn4[i];
    }
    __syncthreads();

    const int NT32 = (N_NODES + 31) / 32;
    for (int t32 = blockIdx.x; t32 < NT32; t32 += gridDim.x) {
        int nb = t32 * 32;
        int vn = min(32, N_NODES - nb);
        int valid_f4 = vn * (DIN / 4);

        const float4* hsrc = (const float4*)(h + (size_t)nb * DIN);
        for (int i = tid; i < 32 * (DIN / 4); i += 256)
            ((float4*)h_sh)[i] = (i < valid_f4) ? hsrc[i] : make_float4(0.f, 0.f, 0.f, 0.f);
        __syncthreads();

        int row = ty * 4;
        float2 as0 = {0,0}, as1 = {0,0}, as2 = {0,0}, as3 = {0,0};
        float2 at0 = {0,0}, at1 = {0,0}, at2 = {0,0}, at3 = {0,0};
        const float4* h0 = (const float4*)(h_sh + (row + 0) * DIN);
        const float4* h1 = (const float4*)(h_sh + (row + 1) * DIN);
        const float4* h2 = (const float4*)(h_sh + (row + 2) * DIN);
        const float4* h3 = (const float4*)(h_sh + (row + 3) * DIN);

        #pragma unroll 4
        for (int kq = 0; kq < DIN / 4; ++kq) {
            float4 v0 = h0[kq], v1 = h1[kq], v2 = h2[kq], v3 = h3[kq];
            const float* e0 = (const float*)&v0;
            const float* e1 = (const float*)&v1;
            const float* e2 = (const float*)&v2;
            const float* e3 = (const float*)&v3;
            #pragma unroll
            for (int j = 0; j < 4; ++j) {
                int k = kq * 4 + j;
                float2 wsv = *(const float2*)&ws_sh[k * 64 + 2 * tx];
                float2 wnv = *(const float2*)&wn_sh[k * 64 + 2 * tx];
                float a0 = e0[j], a1 = e1[j], a2 = e2[j], a3 = e3[j];
                as0.x = fmaf(a0, wsv.x, as0.x); as0.y = fmaf(a0, wsv.y, as0.y);
                as1.x = fmaf(a1, wsv.x, as1.x); as1.y = fmaf(a1, wsv.y, as1.y);
                as2.x = fmaf(a2, wsv.x, as2.x); as2.y = fmaf(a2, wsv.y, as2.y);
                as3.x = fmaf(a3, wsv.x, as3.x); as3.y = fmaf(a3, wsv.y, as3.y);
                at0.x = fmaf(a0, wnv.x, at0.x); at0.y = fmaf(a0, wnv.y, at0.y);
                at1.x = fmaf(a1, wnv.x, at1.x); at1.y = fmaf(a1, wnv.y, at1.y);
                at2.x = fmaf(a2, wnv.x, at2.x); at2.y = fmaf(a2, wnv.y, at2.y);
                at3.x = fmaf(a3, wnv.x, at3.x); at3.y = fmaf(a3, wnv.y, at3.y);
            }
        }

        #pragma unroll
        for (int n = 0; n < 4; ++n) {
            int node = nb + row + n;
            if (node < N_NODES) {
                float2 sv = (n == 0) ? as0 : (n == 1) ? as1 : (n == 2) ? as2 : as3;
                float2 tv = (n == 0) ? at0 : (n == 1) ? at1 : (n == 2) ? at2 : at3;
                *(float2*)&s_out[(size_t)node * 64 + 2 * tx] = sv;
                *(__half2*)&t_out[(size_t)node * 64 + 2 * tx] = __float22half2_rn(tv);
            }
        }
        __syncthreads();
    }
}

// ---------------- aggregate + combine + normalize ----------------
// HALF-WARP per node: 2 nodes/warp, 16 lanes/node, each lane owns 4 features
// (8B half4 load per edge). Halves the LDG instruction count vs warp-per-node:
// per warp-instruction, 2 edges are serviced (one per half-warp).
__global__ void agg_combine_kernel(const __half* __restrict__ t,
                                   const float* __restrict__ smat,
                                   float* __restrict__ hout) {
    int warp = (blockIdx.x * blockDim.x + threadIdx.x) >> 5;
    int lane = threadIdx.x & 31;
    int sub  = lane >> 4;          // 0 or 1: which node of the pair
    int sl   = lane & 15;          // lane within half-warp
    int node = warp * 2 + sub;
    if (node >= N_NODES) return;

    int beg = g_rowptr[node];
    int end = g_rowptr[node + 1];

    float a0 = 0.f, a1 = 0.f, a2 = 0.f, a3 = 0.f;
    float b0 = 0.f, b1 = 0.f, b2 = 0.f, b3 = 0.f;

    int i = beg;
    for (; i + 2 <= end; i += 2) {
        int s0 = __ldg(&g_csr_src[i]);
        int s1 = __ldg(&g_csr_src[i + 1]);
        uint2 r0 = __ldg((const uint2*)(t + (size_t)s0 * 64 + sl * 4));
        uint2 r1 = __ldg((const uint2*)(t + (size_t)s1 * 64 + sl * 4));
        float2 f00 = __half22float2(*(__half2*)&r0.x);
        float2 f01 = __half22float2(*(__half2*)&r0.y);
        float2 f10 = __half22float2(*(__half2*)&r1.x);
        float2 f11 = __half22float2(*(__half2*)&r1.y);
        a0 += f00.x; a1 += f00.y; a2 += f01.x; a3 += f01.y;
        b0 += f10.x; b1 += f10.y; b2 += f11.x; b3 += f11.y;
    }
    if (i < end) {
        int s0 = __ldg(&g_csr_src[i]);
        uint2 r0 = __ldg((const uint2*)(t + (size_t)s0 * 64 + sl * 4));
        float2 f00 = __half22float2(*(__half2*)&r0.x);
        float2 f01 = __half22float2(*(__half2*)&r0.y);
        a0 += f00.x; a1 += f00.y; a2 += f01.x; a3 += f01.y;
    }
    a0 += b0; a1 += b1; a2 += b2; a3 += b3;

    float id = g_invdeg[node];
    float4 sm = __ldg((const float4*)(smat + (size_t)node * 64 + sl * 4));
    float v0 = fmaxf(sm.x + a0 * id, 0.f);
    float v1 = fmaxf(sm.y + a1 * id, 0.f);
    float v2 = fmaxf(sm.z + a2 * id, 0.f);
    float v3 = fmaxf(sm.w + a3 * id, 0.f);

    float ss = v0 * v0 + v1 * v1 + v2 * v2 + v3 * v3;
    #pragma unroll
    for (int o = 8; o; o >>= 1) ss += __shfl_xor_sync(0xffffffffu, ss, o);
    float scale = 1.f / (sqrtf(ss) + EPS);

    float4 r;
    r.x = v0 * scale; r.y = v1 * scale; r.z = v2 * scale; r.w = v3 * scale;
    *(float4*)(hout + (size_t)node * 64 + sl * 4) = r;
}

// ---------------- MLP head: relu(h@mw1+mb1) -> sigmoid(.@mw2+mb2) ----------------
__global__ void head_kernel(const float* __restrict__ h,
                            const float* __restrict__ mw1,
                            const float* __restrict__ mb1,
                            const float* __restrict__ mw2,
                            const float* __restrict__ mb2,
                            float* __restrict__ out) {
    __shared__ float w1s[64 * 32];
    __shared__ float b1s[32];
    __shared__ float w2s[32];
    __shared__ float b2s;

    int tid = threadIdx.x;
    for (int i = tid; i < 64 * 32; i += blockDim.x) w1s[i] = mw1[i];
    if (tid < 32) { b1s[tid] = mb1[tid]; w2s[tid] = mw2[tid]; }
    if (tid == 0) b2s = mb2[0];
    __syncthreads();

    int lane = tid & 31;
    int warp0 = (blockIdx.x * blockDim.x + tid) >> 5;
    int nwarps = (gridDim.x * blockDim.x) >> 5;

    for (int node = warp0; node < N_NODES; node += nwarps) {
        float h0 = h[(size_t)node * 64 + lane];
        float h1 = h[(size_t)node * 64 + lane + 32];

        float acc = b1s[lane];
        #pragma unroll
        for (int k = 0; k < 32; ++k) {
            float hk = __shfl_sync(0xffffffffu, h0, k);
            acc = fmaf(hk, w1s[k * 32 + lane], acc);
        }
        #pragma unroll
        for (int k = 0; k < 32; ++k) {
            float hk = __shfl_sync(0xffffffffu, h1, k);
            acc = fmaf(hk, w1s[(k + 32) * 32 + lane], acc);
        }
        acc = fmaxf(acc, 0.f);

        float p = acc * w2s[lane];
        #pragma unroll
        for (int o = 16; o; o >>= 1) p += __shfl_xor_sync(0xffffffffu, p, o);

        if (lane == 0) {
            float z = p + b2s;
            out[node] = 1.f / (1.f + __expf(-z));
        }
    }
}

// ---------------- launch ----------------
extern "C" void kernel_launch(void* const* d_in, const int* in_sizes, int n_in,
                              void* d_out, int out_size) {
    const float* x   = (const float*)d_in[0];
    const void*  ei  = (const void*)d_in[1];   // int32 or int64, detected on device
    const float* w0s = (const float*)d_in[2];
    const float* w0n = (const float*)d_in[3];
    const float* w1s = (const float*)d_in[4];
    const float* w1n = (const float*)d_in[5];
    const float* w2s = (const float*)d_in[6];
    const float* w2n = (const float*)d_in[7];
    const float* mw1 = (const float*)d_in[8];
    const float* mb1 = (const float*)d_in[9];
    const float* mw2 = (const float*)d_in[10];
    const float* mb2 = (const float*)d_in[11];
    float* out = (float*)d_out;

    float *d_s, *d_hA, *d_hB;
    __half* d_th;
    cudaGetSymbolAddress((void**)&d_s,  g_s);
    cudaGetSymbolAddress((void**)&d_th, g_th);
    cudaGetSymbolAddress((void**)&d_hA, g_hA);
    cudaGetSymbolAddress((void**)&d_hB, g_hB);

    const int SMEM128 = 128 * 160 * 4;   // 81920
    const int SMEM64  = 64 * 160 * 4;    // 40960
    cudaFuncSetAttribute(dual_gemm_kernel<128>,
                         cudaFuncAttributeMaxDynamicSharedMemorySize, SMEM128);
    cudaFuncSetAttribute(dual_gemm_kernel<64>,
                         cudaFuncAttributeMaxDynamicSharedMemorySize, SMEM64);

    const int EB = (N_EDGES + 255) / 256;
    const int NB = (N_NODES + 255) / 256;
    const int GEMM_BLOCKS = 296;                       // 2 per SM, persistent
    const int AB = (N_NODES * 16 + 255) / 256;         // half-warp per node

    // CSR build (once per launch)
    init_kernel<<<NB, 256>>>(ei);
    count_deg_kernel<<<EB, 256>>>(ei);
    scan_fused_kernel<<<NTILES, 1024>>>();
    fill_csr_kernel<<<EB, 256>>>(ei);

    // layer 0 (input x, DIN=128)
    dual_gemm_kernel<128><<<GEMM_BLOCKS, 256, SMEM128>>>(x, w0s, w0n, d_s, d_th);
    agg_combine_kernel<<<AB, 256>>>(d_th, d_s, d_hA);

    // layer 1
    dual_gemm_kernel<64><<<GEMM_BLOCKS, 256, SMEM64>>>(d_hA, w1s, w1n, d_s, d_th);
    agg_combine_kernel<<<AB, 256>>>(d_th, d_s, d_hB);

    // layer 2
    dual_gemm_kernel<64><<<GEMM_BLOCKS, 256, SMEM64>>>(d_hB, w2s, w2n, d_s, d_th);
    agg_combine_kernel<<<AB, 256>>>(d_th, d_s, d_hA);

    // head
    head_kernel<<<1024, 256>>>(d_hA, mw1, mb1, mw2, mb2, out);
}

// round 12
// speedup vs baseline: 1.1140x; 1.0031x over previous
#include <cuda_runtime.h>
#include <cuda_fp16.h>
#include <cuda_bf16.h>
#include <math.h>

#define N_NODES 50000
#define N_EDGES 1600000
#define IN_DIM  128
#define HID     64
#define EPS     1e-6f

#define SCAN_T   1024
#define NTILES   ((N_NODES + SCAN_T - 1) / SCAN_T)   // 49
#define FLAG     (1 << 30)
#define VMASK    (FLAG - 1)

// ---------------- scratch (no allocations allowed) ----------------
__device__ int   g_is64;
__device__ int   g_deg[N_NODES];
__device__ int   g_rowptr[N_NODES + 1];
__device__ int   g_cursor[N_NODES];
__device__ float g_invdeg[N_NODES];
__device__ int   g_csr_src[N_EDGES];
__device__ int   g_tile_state[64];

__device__ float  g_s[N_NODES * HID];
__device__ __half g_th[N_NODES * HID];
__device__ float  g_hA[N_NODES * HID];
__device__ float  g_hB[N_NODES * HID];

__device__ __forceinline__ int edge_at(const void* __restrict__ ei, int idx, int is64) {
    if (is64) return (int)((const long long*)ei)[idx];
    return ((const int*)ei)[idx];
}

// ---- f32x2 packed FMA helpers ----
__device__ __forceinline__ unsigned long long pk2(float lo, float hi) {
    unsigned long long r;
    asm("mov.b64 %0, {%1, %2};" : "=l"(r) : "f"(lo), "f"(hi));
    return r;
}
__device__ __forceinline__ void fma2(unsigned long long& d, unsigned long long a, unsigned long long b) {
    asm("fma.rn.f32x2 %0, %1, %2, %0;" : "+l"(d) : "l"(a), "l"(b));
}
__device__ __forceinline__ float fold2(unsigned long long p) {
    float lo, hi;
    asm("mov.b64 {%0, %1}, %2;" : "=f"(lo), "=f"(hi) : "l"(p));
    return lo + hi;
}

// ---------------- init: zero deg + lookback state, detect edge dtype ----------------
__global__ void init_kernel(const void* __restrict__ ei) {
    int i = blockIdx.x * blockDim.x + threadIdx.x;
    if (i < N_NODES) g_deg[i] = 0;
    if (blockIdx.x == 1 && threadIdx.x < 64) g_tile_state[threadIdx.x] = 0;
    if (blockIdx.x == 0) {
        const long long* p = (const long long*)ei;
        long long v = p[threadIdx.x];
        int bad = (v < 0 || v >= (long long)N_NODES) ? 1 : 0;
        int anybad = __syncthreads_or(bad);
        if (threadIdx.x == 0) g_is64 = anybad ? 0 : 1;
    }
}

__global__ void count_deg_kernel(const void* __restrict__ ei) {
    int e = blockIdx.x * blockDim.x + threadIdx.x;
    int is64 = g_is64;
    if (e < N_EDGES) {
        int dst = edge_at(ei, N_EDGES + e, is64);
        atomicAdd(&g_deg[dst], 1);
    }
}

// ---------------- fused scan: decoupled lookback ----------------
__global__ void scan_fused_kernel() {
    __shared__ int warp_sums[32];
    __shared__ int red[2];
    __shared__ int s_pref;
    int b = blockIdx.x, tid = threadIdx.x;
    int lane = tid & 31, wid = tid >> 5;
    int idx = b * SCAN_T + tid;
    int d = (idx < N_NODES) ? g_deg[idx] : 0;

    int v = d;
    #pragma unroll
    for (int o = 1; o < 32; o <<= 1) {
        int u = __shfl_up_sync(0xffffffffu, v, o);
        if (lane >= o) v += u;
    }
    if (lane == 31) warp_sums[wid] = v;
    __syncthreads();
    if (wid == 0) {
        int w = warp_sums[lane];
        #pragma unroll
        for (int o = 1; o < 32; o <<= 1) {
            int u = __shfl_up_sync(0xffffffffu, w, o);
            if (lane >= o) w += u;
        }
        warp_sums[lane] = w;
    }
    __syncthreads();

    if (tid == 0) atomicExch(&g_tile_state[b], warp_sums[31] | FLAG);

    if (tid < 64) {
        int val = 0;
        if (tid < b) {
            int t;
            do { t = atomicAdd(&g_tile_state[tid], 0); } while (!(t & FLAG));
            val = t & VMASK;
        }
        #pragma unroll
        for (int o = 16; o; o >>= 1) val += __shfl_xor_sync(0xffffffffu, val, o);
        if ((tid & 31) == 0) red[tid >> 5] = val;
    }
    __syncthreads();
    if (tid == 0) s_pref = red[0] + red[1];
    __syncthreads();

    if (idx < N_NODES) {
        int excl = s_pref + (v - d) + (wid ? warp_sums[wid - 1] : 0);
        g_rowptr[idx] = excl;
        g_cursor[idx] = excl;
        g_invdeg[idx] = 1.0f / (float)max(d, 1);
    }
    if (b == 0 && tid == 0) g_rowptr[N_NODES] = N_EDGES;
}

__global__ void fill_csr_kernel(const void* __restrict__ ei) {
    int e = blockIdx.x * blockDim.x + threadIdx.x;
    int is64 = g_is64;
    if (e < N_EDGES) {
        int src = edge_at(ei, e, is64);
        int dst = edge_at(ei, N_EDGES + e, is64);
        int pos = atomicAdd(&g_cursor[dst], 1);
        g_csr_src[pos] = src;
    }
}

// ---------------- persistent dual GEMM with FFMA2 (f32x2) ----------------
// Weights re-staged in smem as k-pair-interleaved: [k/2][64 cols][2(k0,k1)],
// so one LDS.128 per thread gives 2 aligned (k0,k1) operand pairs for 2 cols.
// Accumulator pairs hold (even-k, odd-k) partials; folded at the end.
template<int DIN>
__global__ __launch_bounds__(256, 2)
void dual_gemm_kernel(const float* __restrict__ h,
                      const float* __restrict__ ws,
                      const float* __restrict__ wn,
                      float* __restrict__ s_out,
                      __half* __restrict__ t_out) {
    extern __shared__ float smem[];
    float* ws_p = smem;                        // DIN*64 (pair-interleaved)
    float* wn_p = smem + DIN * 64;             // DIN*64
    float* h_sh = smem + 2 * DIN * 64;         // 32*DIN

    int tid = threadIdx.x;
    int tx  = tid & 31;                         // cols 2tx, 2tx+1
    int ty  = tid >> 5;                         // nodes 4ty..4ty+3

    // stage weights with k-pair transpose: dst[(k>>1)*128 + c*2 + (k&1)] = w[k][c]
    for (int i = tid; i < DIN * 64; i += 256) {
        int k = i >> 6, c = i & 63;
        float vs = ws[i], vn = wn[i];
        int d = ((k >> 1) << 7) + (c << 1) + (k & 1);
        ws_p[d] = vs;
        wn_p[d] = vn;
    }
    __syncthreads();

    const float4* ws_p4 = (const float4*)ws_p;
    const float4* wn_p4 = (const float4*)wn_p;

    const int NT32 = (N_NODES + 31) / 32;
    for (int t32 = blockIdx.x; t32 < NT32; t32 += gridDim.x) {
        int nb = t32 * 32;
        int vn_ = min(32, N_NODES - nb);
        int valid_f4 = vn_ * (DIN / 4);

        const float4* hsrc = (const float4*)(h + (size_t)nb * DIN);
        for (int i = tid; i < 32 * (DIN / 4); i += 256)
            ((float4*)h_sh)[i] = (i < valid_f4) ? hsrc[i] : make_float4(0.f, 0.f, 0.f, 0.f);
        __syncthreads();

        int row = ty * 4;
        const float4* h0 = (const float4*)(h_sh + (row + 0) * DIN);
        const float4* h1 = (const float4*)(h_sh + (row + 1) * DIN);
        const float4* h2 = (const float4*)(h_sh + (row + 2) * DIN);
        const float4* h3 = (const float4*)(h_sh + (row + 3) * DIN);

        unsigned long long sc0[4] = {0,0,0,0}, sc1[4] = {0,0,0,0};
        unsigned long long tc0[4] = {0,0,0,0}, tc1[4] = {0,0,0,0};

        #pragma unroll 2
        for (int kq = 0; kq < DIN / 4; ++kq) {
            float4 v0 = h0[kq], v1 = h1[kq], v2 = h2[kq], v3 = h3[kq];
            float4 wsA = ws_p4[(2 * kq) * 32 + tx];
            float4 wsB = ws_p4[(2 * kq + 1) * 32 + tx];
            float4 wnA = wn_p4[(2 * kq) * 32 + tx];
            float4 wnB = wn_p4[(2 * kq + 1) * 32 + tx];

            unsigned long long wsA0 = pk2(wsA.x, wsA.y), wsA1 = pk2(wsA.z, wsA.w);
            unsigned long long wsB0 = pk2(wsB.x, wsB.y), wsB1 = pk2(wsB.z, wsB.w);
            unsigned long long wnA0 = pk2(wnA.x, wnA.y), wnA1 = pk2(wnA.z, wnA.w);
            unsigned long long wnB0 = pk2(wnB.x, wnB.y), wnB1 = pk2(wnB.z, wnB.w);

            unsigned long long aA[4], aB[4];
            aA[0] = pk2(v0.x, v0.y); aB[0] = pk2(v0.z, v0.w);
            aA[1] = pk2(v1.x, v1.y); aB[1] = pk2(v1.z, v1.w);
            aA[2] = pk2(v2.x, v2.y); aB[2] = pk2(v2.z, v2.w);
            aA[3] = pk2(v3.x, v3.y); aB[3] = pk2(v3.z, v3.w);

            #pragma unroll
            for (int n = 0; n < 4; ++n) {
                fma2(sc0[n], aA[n], wsA0); fma2(sc1[n], aA[n], wsA1);
                fma2(tc0[n], aA[n], wnA0); fma2(tc1[n], aA[n], wnA1);
                fma2(sc0[n], aB[n], wsB0); fma2(sc1[n], aB[n], wsB1);
                fma2(tc0[n], aB[n], wnB0); fma2(tc1[n], aB[n], wnB1);
            }
        }

        #pragma unroll
        for (int n = 0; n < 4; ++n) {
            int node = nb + row + n;
            if (node < N_NODES) {
                float2 sv; sv.x = fold2(sc0[n]); sv.y = fold2(sc1[n]);
                float2 tv; tv.x = fold2(tc0[n]); tv.y = fold2(tc1[n]);
                *(float2*)&s_out[(size_t)node * 64 + 2 * tx] = sv;
                *(__half2*)&t_out[(size_t)node * 64 + 2 * tx] = __float22half2_rn(tv);
            }
        }
        __syncthreads();
    }
}

// ---------------- aggregate + combine + normalize ----------------
// QUARTER-WARP per node: 4 nodes/warp, 8 lanes/node, lane owns 8 features
// (16B LDG.128 per edge). Per warp-instruction, 4 edges serviced.
__global__ void agg_combine_kernel(const __half* __restrict__ t,
                                   const float* __restrict__ smat,
                                   float* __restrict__ hout) {
    int warp = (blockIdx.x * blockDim.x + threadIdx.x) >> 5;
    int lane = threadIdx.x & 31;
    int sub  = lane >> 3;          // 0..3: node within warp
    int sl   = lane & 7;           // lane within 8-lane group
    int node = warp * 4 + sub;
    if (node >= N_NODES) return;

    int beg = g_rowptr[node];
    int end = g_rowptr[node + 1];

    float a0=0.f,a1=0.f,a2=0.f,a3=0.f,a4=0.f,a5=0.f,a6=0.f,a7=0.f;

    int i = beg;
    for (; i + 2 <= end; i += 2) {
        int s0 = __ldg(&g_csr_src[i]);
        int s1 = __ldg(&g_csr_src[i + 1]);
        uint4 r0 = __ldg((const uint4*)(t + (size_t)s0 * 64 + sl * 8));
        uint4 r1 = __ldg((const uint4*)(t + (size_t)s1 * 64 + sl * 8));
        float2 f0 = __half22float2(*(__half2*)&r0.x);
        float2 f1 = __half22float2(*(__half2*)&r0.y);
        float2 f2 = __half22float2(*(__half2*)&r0.z);
        float2 f3 = __half22float2(*(__half2*)&r0.w);
        a0 += f0.x; a1 += f0.y; a2 += f1.x; a3 += f1.y;
        a4 += f2.x; a5 += f2.y; a6 += f3.x; a7 += f3.y;
        float2 g0 = __half22float2(*(__half2*)&r1.x);
        float2 g1 = __half22float2(*(__half2*)&r1.y);
        float2 g2 = __half22float2(*(__half2*)&r1.z);
        float2 g3 = __half22float2(*(__half2*)&r1.w);
        a0 += g0.x; a1 += g0.y; a2 += g1.x; a3 += g1.y;
        a4 += g2.x; a5 += g2.y; a6 += g3.x; a7 += g3.y;
    }
    if (i < end) {
        int s0 = __ldg(&g_csr_src[i]);
        uint4 r0 = __ldg((const uint4*)(t + (size_t)s0 * 64 + sl * 8));
        float2 f0 = __half22float2(*(__half2*)&r0.x);
        float2 f1 = __half22float2(*(__half2*)&r0.y);
        float2 f2 = __half22float2(*(__half2*)&r0.z);
        float2 f3 = __half22float2(*(__half2*)&r0.w);
        a0 += f0.x; a1 += f0.y; a2 += f1.x; a3 += f1.y;
        a4 += f2.x; a5 += f2.y; a6 += f3.x; a7 += f3.y;
    }

    float id = g_invdeg[node];
    float4 sm0 = __ldg((const float4*)(smat + (size_t)node * 64 + sl * 8));
    float4 sm1 = __ldg((const float4*)(smat + (size_t)node * 64 + sl * 8 + 4));
    float v0 = fmaxf(sm0.x + a0 * id, 0.f);
    float v1 = fmaxf(sm0.y + a1 * id, 0.f);
    float v2 = fmaxf(sm0.z + a2 * id, 0.f);
    float v3 = fmaxf(sm0.w + a3 * id, 0.f);
    float v4 = fmaxf(sm1.x + a4 * id, 0.f);
    float v5 = fmaxf(sm1.y + a5 * id, 0.f);
    float v6 = fmaxf(sm1.z + a6 * id, 0.f);
    float v7 = fmaxf(sm1.w + a7 * id, 0.f);

    float ss = v0*v0 + v1*v1 + v2*v2 + v3*v3 + v4*v4 + v5*v5 + v6*v6 + v7*v7;
    #pragma unroll
    for (int o = 4; o; o >>= 1) ss += __shfl_xor_sync(0xffffffffu, ss, o);
    float scale = 1.f / (sqrtf(ss) + EPS);

    float4 r0o, r1o;
    r0o.x = v0 * scale; r0o.y = v1 * scale; r0o.z = v2 * scale; r0o.w = v3 * scale;
    r1o.x = v4 * scale; r1o.y = v5 * scale; r1o.z = v6 * scale; r1o.w = v7 * scale;
    *(float4*)(hout + (size_t)node * 64 + sl * 8)     = r0o;
    *(float4*)(hout + (size_t)node * 64 + sl * 8 + 4) = r1o;
}

// ---------------- MLP head ----------------
__global__ void head_kernel(const float* __restrict__ h,
                            const float* __restrict__ mw1,
                            const float* __restrict__ mb1,
                            const float* __restrict__ mw2,
                            const float* __restrict__ mb2,
                            float* __restrict__ out) {
    __shared__ float w1s[64 * 32];
    __shared__ float b1s[32];
    __shared__ float w2s[32];
    __shared__ float b2s;

    int tid = threadIdx.x;
    for (int i = tid; i < 64 * 32; i += blockDim.x) w1s[i] = mw1[i];
    if (tid < 32) { b1s[tid] = mb1[tid]; w2s[tid] = mw2[tid]; }
    if (tid == 0) b2s = mb2[0];
    __syncthreads();

    int lane = tid & 31;
    int warp0 = (blockIdx.x * blockDim.x + tid) >> 5;
    int nwarps = (gridDim.x * blockDim.x) >> 5;

    for (int node = warp0; node < N_NODES; node += nwarps) {
        float h0 = h[(size_t)node * 64 + lane];
        float h1 = h[(size_t)node * 64 + lane + 32];

        float acc = b1s[lane];
        #pragma unroll
        for (int k = 0; k < 32; ++k) {
            float hk = __shfl_sync(0xffffffffu, h0, k);
            acc = fmaf(hk, w1s[k * 32 + lane], acc);
        }
        #pragma unroll
        for (int k = 0; k < 32; ++k) {
            float hk = __shfl_sync(0xffffffffu, h1, k);
            acc = fmaf(hk, w1s[(k + 32) * 32 + lane], acc);
        }
        acc = fmaxf(acc, 0.f);

        float p = acc * w2s[lane];
        #pragma unroll
        for (int o = 16; o; o >>= 1) p += __shfl_xor_sync(0xffffffffu, p, o);

        if (lane == 0) {
            float z = p + b2s;
            out[node] = 1.f / (1.f + __expf(-z));
        }
    }
}

// ---------------- launch ----------------
extern "C" void kernel_launch(void* const* d_in, const int* in_sizes, int n_in,
                              void* d_out, int out_size) {
    const float* x   = (const float*)d_in[0];
    const void*  ei  = (const void*)d_in[1];
    const float* w0s = (const float*)d_in[2];
    const float* w0n = (const float*)d_in[3];
    const float* w1s = (const float*)d_in[4];
    const float* w1n = (const float*)d_in[5];
    const float* w2s = (const float*)d_in[6];
    const float* w2n = (const float*)d_in[7];
    const float* mw1 = (const float*)d_in[8];
    const float* mb1 = (const float*)d_in[9];
    const float* mw2 = (const float*)d_in[10];
    const float* mb2 = (const float*)d_in[11];
    float* out = (float*)d_out;

    float *d_s, *d_hA, *d_hB;
    __half* d_th;
    cudaGetSymbolAddress((void**)&d_s,  g_s);
    cudaGetSymbolAddress((void**)&d_th, g_th);
    cudaGetSymbolAddress((void**)&d_hA, g_hA);
    cudaGetSymbolAddress((void**)&d_hB, g_hB);

    const int SMEM128 = 128 * 160 * 4;   // 81920
    const int SMEM64  = 64 * 160 * 4;    // 40960
    cudaFuncSetAttribute(dual_gemm_kernel<128>,
                         cudaFuncAttributeMaxDynamicSharedMemorySize, SMEM128);
    cudaFuncSetAttribute(dual_gemm_kernel<64>,
                         cudaFuncAttributeMaxDynamicSharedMemorySize, SMEM64);

    const int EB = (N_EDGES + 255) / 256;
    const int NB = (N_NODES + 255) / 256;
    const int GEMM_BLOCKS = 296;                       // 2 per SM, persistent
    const int AB = (N_NODES * 8 + 255) / 256;          // quarter-warp per node

    init_kernel<<<NB, 256>>>(ei);
    count_deg_kernel<<<EB, 256>>>(ei);
    scan_fused_kernel<<<NTILES, 1024>>>();
    fill_csr_kernel<<<EB, 256>>>(ei);

    dual_gemm_kernel<128><<<GEMM_BLOCKS, 256, SMEM128>>>(x, w0s, w0n, d_s, d_th);
    agg_combine_kernel<<<AB, 256>>>(d_th, d_s, d_hA);

    dual_gemm_kernel<64><<<GEMM_BLOCKS, 256, SMEM64>>>(d_hA, w1s, w1n, d_s, d_th);
    agg_combine_kernel<<<AB, 256>>>(d_th, d_s, d_hB);

    dual_gemm_kernel<64><<<GEMM_BLOCKS, 256, SMEM64>>>(d_hB, w2s, w2n, d_s, d_th);
    agg_combine_kernel<<<AB, 256>>>(d_th, d_s, d_hA);

    head_kernel<<<1024, 256>>>(d_hA, mw1, mb1, mw2, mb2, out);
}